// round 16
// baseline (speedup 1.0000x reference)
#include <cuda_runtime.h>
#include <math.h>

// ---------------- problem constants ----------------
constexpr int NN   = 40000;   // nodes
constexpr int EE   = 160000;  // edges
constexpr int GG   = 512;     // graphs
constexpr int HH   = 256;     // hidden
constexpr int NH   = 3;       // heads
constexpr int INF_ = 64;      // in_features
constexpr int EFD  = 16;      // edge_features
constexpr int OUTF = 12;
constexpr int LAY  = 3;
constexpr int STEP = 6;
constexpr int H3   = NH * HH; // 768

// ---------------- scratch layout (single __device__ global) ----------------
constexpr size_t OFF_OUT   = 0;
constexpr size_t OFF_XN    = OFF_OUT   + (size_t)NN * HH;
constexpr size_t OFF_AGGR  = OFF_XN    + (size_t)NN * H3;
constexpr size_t OFF_SDST  = OFF_AGGR  + (size_t)NN * H3;
constexpr size_t OFF_SSRC  = OFF_SDST  + (size_t)NN * NH;
constexpr size_t OFF_ALPHA = OFF_SSRC  + (size_t)NN * NH;
constexpr size_t OFF_NMAX  = OFF_ALPHA + (size_t)EE * NH;
constexpr size_t OFF_NSUM  = OFF_NMAX  + (size_t)NN * NH;
constexpr size_t OFF_U     = OFF_NSUM  + (size_t)NN * NH;
constexpr size_t OFF_WFOLD = OFF_U     + 64;                    // 256*6 + pad
constexpr size_t OFF_WT    = OFF_WFOLD + 1600;                  // 768*1024
constexpr size_t OFF_BSUM  = OFF_WT    + (size_t)768 * 1024;
constexpr size_t OFF_C     = OFF_BSUM  + 1024;
constexpr size_t OFF_QS    = OFF_C     + (size_t)GG * HH;
constexpr size_t OFF_Z     = OFF_QS    + (size_t)GG * 2 * HH;
constexpr size_t OFF_GATES = OFF_Z     + (size_t)GG * 768;
constexpr size_t OFF_E     = OFF_GATES + (size_t)GG * 1024;
constexpr size_t OFF_BND   = OFF_E     + NN;                    // 513 ints (as floats)
constexpr size_t TOTAL_F   = OFF_BND   + 520;

__device__ float g_scratch[TOTAL_F];

// ---------------- helpers ----------------
__device__ __forceinline__ float sigmoidf_(float x) { return 1.0f / (1.0f + expf(-x)); }

__device__ __forceinline__ void atomicMaxFloat(float* addr, float val) {
    int* ia = (int*)addr;
    int old = *ia;
    while (__int_as_float(old) < val) {
        int assumed = old;
        old = atomicCAS(ia, assumed, __float_as_int(val));
        if (old == assumed) break;
    }
}

__device__ __forceinline__ unsigned f2tf32(float x) {
    unsigned r;
    asm("cvt.rna.tf32.f32 %0, %1;" : "=r"(r) : "f"(x));
    return r;
}

__device__ __forceinline__ void split_tf32(float x, unsigned& hi, unsigned& lo) {
    hi = f2tf32(x);
    lo = f2tf32(x - __uint_as_float(hi));
}

__device__ __forceinline__ void mma_tf32(float* c, const unsigned* a, const unsigned* b) {
    asm volatile(
        "mma.sync.aligned.m16n8k8.row.col.f32.tf32.tf32.f32 "
        "{%0,%1,%2,%3}, {%4,%5,%6,%7}, {%8,%9}, {%0,%1,%2,%3};\n"
        : "+f"(c[0]), "+f"(c[1]), "+f"(c[2]), "+f"(c[3])
        : "r"(a[0]), "r"(a[1]), "r"(a[2]), "r"(a[3]), "r"(b[0]), "r"(b[1]));
}

// ---------- 3xTF32 tensor-core GEMM, BM=128 BN=64, 2 CTAs/SM: C = A[M,K]@B[K,N] ----------
// 8 warps in 4(m) x 2(n); warp tile 32x32. BOTH A and B pre-split hi/lo into dynamic smem
// at tile-store time -> inner loop is pure LDS + MMA. Requires N % 64 == 0, K % 16 == 0.
// Dynamic smem: (2*16*136*2 + 2*16*72*2) * 4 = 53248 bytes.
constexpr int GEMM_SA = 136, GEMM_SB = 72, GEMM_BK = 16;
constexpr int GEMM_SMEM = (2 * GEMM_BK * GEMM_SA * 2 + 2 * GEMM_BK * GEMM_SB * 2) * 4;

__global__ void __launch_bounds__(256, 2)
sgemm_tc(const float* __restrict__ A, const float* __restrict__ B,
         float* __restrict__ C, int M, int N, int K,
         const float* __restrict__ bias, int mode) {
    constexpr int BM = 128, BK = GEMM_BK, SA = GEMM_SA, SB = GEMM_SB;
    extern __shared__ unsigned dsm[];
    unsigned* Ah = dsm;                       // [2][BK][SA]
    unsigned* Al = Ah + 2 * BK * SA;
    unsigned* Bh = Al + 2 * BK * SA;          // [2][BK][SB]
    unsigned* Bl = Bh + 2 * BK * SB;

    const int tid  = threadIdx.x;
    const int warp = tid >> 5, lane = tid & 31;
    const int gid  = lane >> 2, tig = lane & 3;
    const int wm   = (warp & 3) * 32;   // 4 warps along M
    const int wn   = (warp >> 2) * 32;  // 2 warps along N
    const int bm   = blockIdx.y * BM;
    const int bn   = blockIdx.x * 64;

    float acc[2][4][4];
#pragma unroll
    for (int mt = 0; mt < 2; mt++)
#pragma unroll
        for (int nt = 0; nt < 4; nt++)
#pragma unroll
            for (int r = 0; r < 4; r++) acc[mt][nt][r] = 0.f;

    float4 a_reg[2], b_reg;

    auto loadA = [&](int k0) {
#pragma unroll
        for (int j = 0; j < 2; j++) {
            int f = tid + j * 256;          // 0..511
            int row = f >> 2;               // 0..127
            int c4 = (f & 3) << 2;          // 0,4,8,12
            if (bm + row < M)
                a_reg[j] = *(const float4*)(A + (size_t)(bm + row) * K + k0 + c4);
            else
                a_reg[j] = make_float4(0.f, 0.f, 0.f, 0.f);
        }
    };
    auto storeA = [&](int buf) {
#pragma unroll
        for (int j = 0; j < 2; j++) {
            int f = tid + j * 256;
            int row = f >> 2;
            int c4 = (f & 3) << 2;
            float v[4] = {a_reg[j].x, a_reg[j].y, a_reg[j].z, a_reg[j].w};
#pragma unroll
            for (int i = 0; i < 4; i++) {
                unsigned hi, lo;
                split_tf32(v[i], hi, lo);
                int idx = (buf * BK + c4 + i) * SA + row;
                Ah[idx] = hi;
                Al[idx] = lo;
            }
        }
    };
    auto loadB = [&](int k0) {
        int krow = tid >> 4;                // 0..15
        int c4 = (tid & 15) << 2;           // 0..60
        b_reg = *(const float4*)(B + (size_t)(k0 + krow) * N + bn + c4);
    };
    auto storeB = [&](int buf) {
        int krow = tid >> 4;
        int c4 = (tid & 15) << 2;
        float v[4] = {b_reg.x, b_reg.y, b_reg.z, b_reg.w};
#pragma unroll
        for (int i = 0; i < 4; i++) {
            unsigned hi, lo;
            split_tf32(v[i], hi, lo);
            int idx = (buf * BK + krow) * SB + c4 + i;
            Bh[idx] = hi;
            Bl[idx] = lo;
        }
    };

    const int KT = K / BK;
    loadA(0); loadB(0);
    storeA(0); storeB(0);
    __syncthreads();

    int cur = 0;
    for (int t = 0; t < KT; t++) {
        if (t + 1 < KT) { loadA((t + 1) * BK); loadB((t + 1) * BK); }
#pragma unroll
        for (int ks = 0; ks < 2; ks++) {
            int k0 = ks * 8;
            unsigned ah[2][4], al[2][4], bh[4][2], bl[4][2];
#pragma unroll
            for (int mt = 0; mt < 2; mt++) {
                int m0 = wm + mt * 16 + gid;
                int i0 = (cur * BK + k0 + tig) * SA + m0;
                int i1 = (cur * BK + k0 + tig + 4) * SA + m0;
                ah[mt][0] = Ah[i0];     al[mt][0] = Al[i0];
                ah[mt][1] = Ah[i0 + 8]; al[mt][1] = Al[i0 + 8];
                ah[mt][2] = Ah[i1];     al[mt][2] = Al[i1];
                ah[mt][3] = Ah[i1 + 8]; al[mt][3] = Al[i1 + 8];
            }
#pragma unroll
            for (int nt = 0; nt < 4; nt++) {
                int n0 = wn + nt * 8 + gid;
                int i0 = (cur * BK + k0 + tig) * SB + n0;
                int i1 = (cur * BK + k0 + tig + 4) * SB + n0;
                bh[nt][0] = Bh[i0]; bh[nt][1] = Bh[i1];
                bl[nt][0] = Bl[i0]; bl[nt][1] = Bl[i1];
            }
#pragma unroll
            for (int mt = 0; mt < 2; mt++)
#pragma unroll
                for (int nt = 0; nt < 4; nt++) {
                    mma_tf32(acc[mt][nt], al[mt], bh[nt]);
                    mma_tf32(acc[mt][nt], ah[mt], bl[nt]);
                    mma_tf32(acc[mt][nt], ah[mt], bh[nt]);
                }
        }
        if (t + 1 < KT) {
            storeA(cur ^ 1); storeB(cur ^ 1);
            __syncthreads();
            cur ^= 1;
        }
    }

    // epilogue
#pragma unroll
    for (int mt = 0; mt < 2; mt++) {
#pragma unroll
        for (int nt = 0; nt < 4; nt++) {
            int col = bn + wn + nt * 8 + 2 * tig;
            float bv0 = 0.f, bv1 = 0.f;
            if (mode != 0) { bv0 = bias[col]; bv1 = bias[col + 1]; }
#pragma unroll
            for (int half = 0; half < 2; half++) {
                int row = bm + wm + mt * 16 + gid + half * 8;
                if (row >= M) continue;
                float v0 = acc[mt][nt][half * 2 + 0];
                float v1 = acc[mt][nt][half * 2 + 1];
                size_t cidx = (size_t)row * N + col;
                if (mode == 1) {
                    v0 += bv0; v1 += bv1;
                    v0 = v0 > 0.f ? v0 : expm1f(v0);
                    v1 = v1 > 0.f ? v1 : expm1f(v1);
                } else if (mode == 2) {
                    v0 += bv0 + C[cidx]; v1 += bv1 + C[cidx + 1];
                } else if (mode == 3) {
                    v0 += bv0; v1 += bv1;
                }
                *(float2*)(C + cidx) = make_float2(v0, v1);
            }
        }
    }
}

// ---------------- folded attention score weights ----------------
// wfold[k, h*2+0] = sum_d Wn_l[k, h*H+d] * wa[h, d]        (dst)
// wfold[k, h*2+1] = sum_d Wn_l[k, h*H+d] * wa[h, 2H+d]     (src)
__global__ void fold_w_kernel(const float* __restrict__ Wn_l, const float* __restrict__ watt_l,
                              float* __restrict__ wfold) {
    int i = blockIdx.x * blockDim.x + threadIdx.x;
    if (i >= HH * 6) return;
    int k = i / 6, j = i - k * 6;
    int h = j >> 1, w = j & 1;
    const float* wn = Wn_l + (size_t)k * H3 + h * HH;
    const float* wa = watt_l + h * 3 * HH + (w ? 2 * HH : 0);
    float a = 0.f;
    for (int d = 0; d < HH; d++) a += wn[d] * wa[d];
    wfold[k * 6 + j] = a;
}

// per-node scores from out (1 KB/node instead of 3 KB xn row): warp per node, 6 dots
__global__ void node_scores_kernel(const float* __restrict__ out, const float* __restrict__ wfold,
                                   float* __restrict__ sdst, float* __restrict__ ssrc) {
    int warp = (blockIdx.x * blockDim.x + threadIdx.x) >> 5;
    int lane = threadIdx.x & 31;
    if (warp >= NN) return;
    const float* orow = out + (size_t)warp * HH;
    float acc[6] = {0.f, 0.f, 0.f, 0.f, 0.f, 0.f};
    for (int d = lane; d < HH; d += 32) {
        float v = orow[d];
        const float* wf = wfold + d * 6;
#pragma unroll
        for (int j = 0; j < 6; j++) acc[j] += v * wf[j];
    }
#pragma unroll
    for (int o = 16; o; o >>= 1)
#pragma unroll
        for (int j = 0; j < 6; j++) acc[j] += __shfl_down_sync(0xffffffffu, acc[j], o);
    if (!lane) {
#pragma unroll
        for (int h = 0; h < NH; h++) {
            sdst[warp * NH + h] = acc[h * 2];
            ssrc[warp * NH + h] = acc[h * 2 + 1];
        }
    }
}

// u[k,h] = sum_d We_l[k, h*H+d] * wa[h, H+d]
__global__ void compute_u_kernel(const float* __restrict__ We_l, const float* __restrict__ watt_l,
                                 float* __restrict__ u) {
    int warp = (blockIdx.x * blockDim.x + threadIdx.x) >> 5;
    int lane = threadIdx.x & 31;
    if (warp >= EFD * NH) return;
    int k = warp / NH, h = warp % NH;
    const float* wr = We_l + (size_t)k * H3 + h * HH;
    const float* wa = watt_l + h * 3 * HH + HH;
    float a = 0.f;
    for (int d = lane; d < HH; d += 32) a += wr[d] * wa[d];
#pragma unroll
    for (int o = 16; o; o >>= 1) a += __shfl_down_sync(0xffffffffu, a, o);
    if (!lane) u[k * NH + h] = a;
}

__global__ void init_nodesm_kernel(float* __restrict__ nmax, float* __restrict__ nsum) {
    int i = blockIdx.x * blockDim.x + threadIdx.x;
    if (i >= NN * NH) return;
    nmax[i] = __int_as_float(0xff800000); // -inf
    nsum[i] = 0.f;
}

// raw attention logits + leaky relu + segment max
__global__ void edge_alpha_kernel(const float* __restrict__ edge_attr,
                                  const int* __restrict__ src, const int* __restrict__ dst,
                                  const float* __restrict__ sdst, const float* __restrict__ ssrc,
                                  const float* __restrict__ u,
                                  float* __restrict__ alpha, float* __restrict__ nmax) {
    int e = blockIdx.x * blockDim.x + threadIdx.x;
    if (e >= EE) return;
    float ea[EFD];
#pragma unroll
    for (int k = 0; k < EFD; k++) ea[k] = edge_attr[(size_t)e * EFD + k];
    int s = src[e], t = dst[e];
#pragma unroll
    for (int h = 0; h < NH; h++) {
        float v = sdst[t * NH + h] + ssrc[s * NH + h];
#pragma unroll
        for (int k = 0; k < EFD; k++) v += ea[k] * u[k * NH + h];
        v = v > 0.f ? v : 0.2f * v;   // leaky_relu(0.2)
        alpha[(size_t)e * NH + h] = v;
        atomicMaxFloat(&nmax[t * NH + h], v);
    }
}

__global__ void edge_exp_kernel(const int* __restrict__ dst, float* __restrict__ alpha,
                                const float* __restrict__ nmax, float* __restrict__ nsum) {
    int i = blockIdx.x * blockDim.x + threadIdx.x;
    if (i >= EE * NH) return;
    int e = i / NH, h = i - e * NH;
    int t = dst[e];
    float ex = expf(alpha[i] - nmax[t * NH + h]);
    alpha[i] = ex;
    atomicAdd(&nsum[t * NH + h], ex);
}

// nsum -> 1/(nsum + eps), in place (NN*NH elements)
__global__ void nsum_inv_kernel(float* __restrict__ nsum) {
    int i = blockIdx.x * blockDim.x + threadIdx.x;
    if (i >= NN * NH) return;
    nsum[i] = 1.f / (nsum[i] + 1e-16f);
}

// per-edge message with vector reductions: aggr[dst] += alpha*ninv * ea * xn[src]
// 192 threads: thread owns 4 consecutive dims (one head each), red.global.add.v4.f32
__global__ void __launch_bounds__(192)
message_kernel(const float* __restrict__ xn, const float* __restrict__ edge_attr,
               const float* __restrict__ We_l, const float* __restrict__ alpha,
               const float* __restrict__ ninv,
               const int* __restrict__ src, const int* __restrict__ dst,
               float* __restrict__ aggr) {
    constexpr int EPB = 32;
    __shared__ float We_s[EFD * H3]; // 49152 bytes
    int tid = threadIdx.x;           // 0..191
    for (int i = tid; i < EFD * H3; i += 192) We_s[i] = We_l[i];
    __syncthreads();
    const float4* We4 = (const float4*)We_s;
    const int d4 = tid * 4;          // dim base, 0..764
    const int head = d4 >> 8;        // 0..2
    int e0 = blockIdx.x * EPB;
    int e1 = min(e0 + EPB, EE);
    for (int e = e0; e < e1; e++) {
        int s = src[e], t = dst[e];
        const float4* e4p = (const float4*)(edge_attr + (size_t)e * EFD);
        float4 q0 = e4p[0], q1 = e4p[1], q2 = e4p[2], q3 = e4p[3];
        float ea[EFD] = {q0.x, q0.y, q0.z, q0.w, q1.x, q1.y, q1.z, q1.w,
                         q2.x, q2.y, q2.z, q2.w, q3.x, q3.y, q3.z, q3.w};
        float coef = alpha[(size_t)e * NH + head] * ninv[t * NH + head];
        float4 eav = make_float4(0.f, 0.f, 0.f, 0.f);
#pragma unroll
        for (int k = 0; k < EFD; k++) {
            float4 wv = We4[k * (H3 / 4) + tid];
            eav.x += ea[k] * wv.x;
            eav.y += ea[k] * wv.y;
            eav.z += ea[k] * wv.z;
            eav.w += ea[k] * wv.w;
        }
        float4 xv = *(const float4*)(xn + (size_t)s * H3 + d4);
        float4 val;
        val.x = coef * eav.x * xv.x;
        val.y = coef * eav.y * xv.y;
        val.z = coef * eav.z * xv.z;
        val.w = coef * eav.w * xv.w;
        float* addr = aggr + (size_t)t * H3 + d4;
        asm volatile("red.global.add.v4.f32 [%0], {%1, %2, %3, %4};"
                     :: "l"(addr), "f"(val.x), "f"(val.y), "f"(val.z), "f"(val.w)
                     : "memory");
    }
}

// ---------------- set2set ----------------
__global__ void transpose_w_kernel(const float* __restrict__ W_ih, const float* __restrict__ W_hh,
                                   float* __restrict__ Wt) {
    int i = blockIdx.x * blockDim.x + threadIdx.x; // 768*1024
    if (i >= 768 * 1024) return;
    int k = i >> 10, j = i & 1023;
    Wt[i] = (k < 512) ? W_ih[(size_t)j * 512 + k] : W_hh[(size_t)j * 256 + (k - 512)];
}

__global__ void bias_sum_kernel(const float* __restrict__ b_ih, const float* __restrict__ b_hh,
                                float* __restrict__ bsum) {
    int j = blockIdx.x * blockDim.x + threadIdx.x;
    if (j < 1024) bsum[j] = b_ih[j] + b_hh[j];
}

// per-graph node range via binary search (batch is sorted)
__global__ void bounds_kernel(const int* __restrict__ batch, int* __restrict__ bounds) {
    int g = blockIdx.x * blockDim.x + threadIdx.x;
    if (g > GG) return;
    int lo = 0, hi = NN;
    while (lo < hi) { int mid = (lo + hi) >> 1; if (batch[mid] < g) lo = mid + 1; else hi = mid; }
    bounds[g] = lo;
}

// fused per-graph: LSTM cell + scores + segment softmax + pooling + q_star/z packing
__global__ void s2s_step_kernel(const float* __restrict__ gates, float* __restrict__ c,
                                const float* __restrict__ out, const int* __restrict__ bounds,
                                float* __restrict__ e_buf, float* __restrict__ z,
                                float* __restrict__ qstar) {
    int g = blockIdx.x, tid = threadIdx.x;      // 512 blocks x 256
    int lane = tid & 31, wid = tid >> 5;
    __shared__ float hs[HH];
    __shared__ float red[8];
    __shared__ float m_s, sum_s;
    int s0 = bounds[g], s1 = bounds[g + 1];

    // LSTM cell (pytorch gate order i,f,g,o)
    const float* gr = gates + (size_t)g * 1024;
    float ii = sigmoidf_(gr[tid]);
    float ff = sigmoidf_(gr[256 + tid]);
    float gg = tanhf(gr[512 + tid]);
    float oo = sigmoidf_(gr[768 + tid]);
    size_t cidx = (size_t)g * 256 + tid;
    float cn = ff * c[cidx] + ii * gg;
    c[cidx] = cn;
    float hv = oo * tanhf(cn);
    hs[tid] = hv;
    __syncthreads();

    // pass 1: e[n] = out[n].h ; block max
    float lmax = __int_as_float(0xff800000);
    for (int n = s0 + wid; n < s1; n += 8) {
        const float* orow = out + (size_t)n * HH;
        float a = 0.f;
        for (int d = lane; d < HH; d += 32) a += orow[d] * hs[d];
#pragma unroll
        for (int o = 16; o; o >>= 1) a += __shfl_down_sync(0xffffffffu, a, o);
        if (!lane) { e_buf[n] = a; lmax = fmaxf(lmax, a); }
    }
    if (!lane) red[wid] = lmax;
    __syncthreads();
    if (tid == 0) {
        float m = red[0];
        for (int w = 1; w < 8; w++) m = fmaxf(m, red[w]);
        if (!isfinite(m)) m = 0.f;
        m_s = m;
    }
    __syncthreads();
    float m = m_s;

    // pass 2: ex = exp(e - m); block sum
    float ls = 0.f;
    for (int n = s0 + tid; n < s1; n += 256) {
        float ex = expf(e_buf[n] - m);
        e_buf[n] = ex;
        ls += ex;
    }
#pragma unroll
    for (int o = 16; o; o >>= 1) ls += __shfl_down_sync(0xffffffffu, ls, o);
    if (!lane) red[wid] = ls;
    __syncthreads();
    if (tid == 0) {
        float s = 0.f;
        for (int w = 0; w < 8; w++) s += red[w];
        sum_s = s;
    }
    __syncthreads();
    float inv = 1.f / (sum_s + 1e-16f);

    // pass 3: r[d] = sum_n ex[n]*out[n][d] * inv
    float r = 0.f;
    int n = s0;
    for (; n + 4 <= s1; n += 4) {
        r += e_buf[n]     * out[(size_t)n * HH + tid]
           + e_buf[n + 1] * out[(size_t)(n + 1) * HH + tid]
           + e_buf[n + 2] * out[(size_t)(n + 2) * HH + tid]
           + e_buf[n + 3] * out[(size_t)(n + 3) * HH + tid];
    }
    for (; n < s1; n++) r += e_buf[n] * out[(size_t)n * HH + tid];
    r *= inv;

    qstar[(size_t)g * 512 + tid]       = hv;
    qstar[(size_t)g * 512 + 256 + tid] = r;
    z[(size_t)g * 768 + tid]           = hv;  // z = [q_star, h] = [h, r, h]
    z[(size_t)g * 768 + 256 + tid]     = r;
    z[(size_t)g * 768 + 512 + tid]     = hv;
}

// ---------------- MLP head: Linear -> LayerNorm -> ReLU -> Linear ----------------
__global__ void head_kernel(const float* __restrict__ qstar, const float* __restrict__ W1,
                            const float* __restrict__ b1, const float* __restrict__ ln_g,
                            const float* __restrict__ ln_b, const float* __restrict__ W2,
                            const float* __restrict__ b2, float* __restrict__ outp) {
    __shared__ float qs[512];
    __shared__ float r1[8], r2[8];
    __shared__ float stats[2];
    __shared__ float accs[OUTF];
    int g = blockIdx.x, tid = threadIdx.x; // 512 blocks x 256
    qs[tid]       = qstar[(size_t)g * 512 + tid];
    qs[tid + 256] = qstar[(size_t)g * 512 + 256 + tid];
    if (tid < OUTF) accs[tid] = 0.f;
    __syncthreads();

    float v = b1[tid];
    for (int k = 0; k < 512; k++) v += qs[k] * W1[(size_t)k * 256 + tid];

    int lane = tid & 31, wid = tid >> 5;
    float s1 = v, s2 = v * v;
#pragma unroll
    for (int o = 16; o; o >>= 1) {
        s1 += __shfl_down_sync(0xffffffffu, s1, o);
        s2 += __shfl_down_sync(0xffffffffu, s2, o);
    }
    if (!lane) { r1[wid] = s1; r2[wid] = s2; }
    __syncthreads();
    if (tid == 0) {
        float t1 = 0.f, t2 = 0.f;
        for (int w = 0; w < 8; w++) { t1 += r1[w]; t2 += r2[w]; }
        float mu = t1 / 256.f;
        float var = t2 / 256.f - mu * mu;
        stats[0] = mu;
        stats[1] = rsqrtf(var + 1e-5f);
    }
    __syncthreads();

    float yln = (v - stats[0]) * stats[1] * ln_g[tid] + ln_b[tid];
    yln = fmaxf(yln, 0.f);

    float p[OUTF];
#pragma unroll
    for (int j = 0; j < OUTF; j++) p[j] = yln * W2[(size_t)tid * OUTF + j];
#pragma unroll
    for (int o = 16; o; o >>= 1)
#pragma unroll
        for (int j = 0; j < OUTF; j++) p[j] += __shfl_down_sync(0xffffffffu, p[j], o);
    if (!lane)
        for (int j = 0; j < OUTF; j++) atomicAdd(&accs[j], p[j]);
    __syncthreads();
    if (tid < OUTF) outp[(size_t)g * OUTF + tid] = accs[tid] + b2[tid];
}

// ---------------- host orchestration ----------------
static void launch_gemm(const float* A, const float* B, float* C, int M, int N, int K,
                        const float* bias, int mode) {
    dim3 grid(N / 64, (M + 127) / 128);
    sgemm_tc<<<grid, 256, GEMM_SMEM>>>(A, B, C, M, N, K, bias, mode);
}

extern "C" void kernel_launch(void* const* d_in, const int* in_sizes, int n_in,
                              void* d_out, int out_size) {
    const float* x         = (const float*)d_in[0];
    const float* edge_attr = (const float*)d_in[1];
    const int*   edge_index= (const int*)d_in[2];
    const int*   batch     = (const int*)d_in[3];
    const float* proj_W    = (const float*)d_in[4];
    const float* proj_b    = (const float*)d_in[5];
    const float* Wn        = (const float*)d_in[6];
    const float* We        = (const float*)d_in[7];
    const float* Watt      = (const float*)d_in[8];
    const float* Ws        = (const float*)d_in[9];
    const float* bl        = (const float*)d_in[10];
    const float* W_ih      = (const float*)d_in[11];
    const float* W_hh      = (const float*)d_in[12];
    const float* b_ih      = (const float*)d_in[13];
    const float* b_hh      = (const float*)d_in[14];
    const float* mlp_W1    = (const float*)d_in[15];
    const float* mlp_b1    = (const float*)d_in[16];
    const float* ln_g      = (const float*)d_in[17];
    const float* ln_b      = (const float*)d_in[18];
    const float* mlp_W2    = (const float*)d_in[19];
    const float* mlp_b2    = (const float*)d_in[20];
    float* outp = (float*)d_out;

    const int* src = edge_index;
    const int* dst = edge_index + EE;

    cudaFuncSetAttribute(sgemm_tc, cudaFuncAttributeMaxDynamicSharedMemorySize, GEMM_SMEM);

    float* S = nullptr;
    cudaGetSymbolAddress((void**)&S, g_scratch);
    float* out_   = S + OFF_OUT;
    float* xn_    = S + OFF_XN;
    float* aggr_  = S + OFF_AGGR;
    float* sdst_  = S + OFF_SDST;
    float* ssrc_  = S + OFF_SSRC;
    float* alpha_ = S + OFF_ALPHA;
    float* nmax_  = S + OFF_NMAX;
    float* nsum_  = S + OFF_NSUM;
    float* u_     = S + OFF_U;
    float* wfold_ = S + OFF_WFOLD;
    float* wt_    = S + OFF_WT;
    float* bsum_  = S + OFF_BSUM;
    float* c_     = S + OFF_C;
    float* qs_    = S + OFF_QS;
    float* z_     = S + OFF_Z;
    float* gates_ = S + OFF_GATES;
    float* e_     = S + OFF_E;
    int*   bnd_   = (int*)(S + OFF_BND);

    // ---- projection: out = celu(x @ proj_W + proj_b) ----
    launch_gemm(x, proj_W, out_, NN, HH, INF_, proj_b, 1);

    // ---- 3 triplet message-passing layers ----
    for (int l = 0; l < LAY; l++) {
        const float* Wn_l = Wn   + (size_t)l * HH * H3;
        const float* We_l = We   + (size_t)l * EFD * H3;
        const float* Wa_l = Watt + (size_t)l * NH * 3 * HH;
        const float* Ws_l = Ws   + (size_t)l * H3 * HH;
        const float* bl_l = bl   + (size_t)l * HH;

        launch_gemm(out_, Wn_l, xn_, NN, H3, HH, nullptr, 0);
        fold_w_kernel<<<6, 256>>>(Wn_l, Wa_l, wfold_);
        node_scores_kernel<<<(NN * 32 + 255) / 256, 256>>>(out_, wfold_, sdst_, ssrc_);
        compute_u_kernel<<<6, 256>>>(We_l, Wa_l, u_);
        init_nodesm_kernel<<<(NN * NH + 255) / 256, 256>>>(nmax_, nsum_);
        edge_alpha_kernel<<<(EE + 255) / 256, 256>>>(edge_attr, src, dst, sdst_, ssrc_, u_,
                                                     alpha_, nmax_);
        edge_exp_kernel<<<(EE * NH + 255) / 256, 256>>>(dst, alpha_, nmax_, nsum_);
        nsum_inv_kernel<<<(NN * NH + 255) / 256, 256>>>(nsum_);
        cudaMemsetAsync(aggr_, 0, (size_t)NN * H3 * sizeof(float));
        message_kernel<<<(EE + 31) / 32, 192>>>(xn_, edge_attr, We_l, alpha_, nsum_, src, dst,
                                                aggr_);
        launch_gemm(aggr_, Ws_l, out_, NN, HH, H3, bl_l, 2);
    }

    // ---- set2set ----
    transpose_w_kernel<<<(768 * 1024 + 255) / 256, 256>>>(W_ih, W_hh, wt_);
    bias_sum_kernel<<<4, 256>>>(b_ih, b_hh, bsum_);
    bounds_kernel<<<3, 256>>>(batch, bnd_);
    cudaMemsetAsync(c_, 0, (size_t)GG * HH * sizeof(float));
    cudaMemsetAsync(z_, 0, (size_t)GG * 768 * sizeof(float));

    for (int s = 0; s < STEP; s++) {
        launch_gemm(z_, wt_, gates_, GG, 1024, 768, bsum_, 3);
        s2s_step_kernel<<<GG, 256>>>(gates_, c_, out_, bnd_, e_, z_, qs_);
    }

    // ---- MLP head ----
    head_kernel<<<GG, 256>>>(qs_, mlp_W1, mlp_b1, ln_g, ln_b, mlp_W2, mlp_b2, outp);
}

// round 17
// speedup vs baseline: 1.1247x; 1.1247x over previous
#include <cuda_runtime.h>
#include <math.h>

// ---------------- problem constants ----------------
constexpr int NN   = 40000;   // nodes
constexpr int EE   = 160000;  // edges
constexpr int GG   = 512;     // graphs
constexpr int HH   = 256;     // hidden
constexpr int NH   = 3;       // heads
constexpr int INF_ = 64;      // in_features
constexpr int EFD  = 16;      // edge_features
constexpr int OUTF = 12;
constexpr int LAY  = 3;
constexpr int STEP = 6;
constexpr int H3   = NH * HH; // 768

// ---------------- scratch layout (single __device__ global) ----------------
constexpr size_t OFF_OUT   = 0;
constexpr size_t OFF_XN    = OFF_OUT   + (size_t)NN * HH;
constexpr size_t OFF_AGGR  = OFF_XN    + (size_t)NN * H3;
constexpr size_t OFF_SDST  = OFF_AGGR  + (size_t)NN * H3;
constexpr size_t OFF_SSRC  = OFF_SDST  + (size_t)NN * NH;
constexpr size_t OFF_ALPHA = OFF_SSRC  + (size_t)NN * NH;
constexpr size_t OFF_NMAX  = OFF_ALPHA + (size_t)EE * NH;
constexpr size_t OFF_NSUM  = OFF_NMAX  + (size_t)NN * NH;
constexpr size_t OFF_U     = OFF_NSUM  + (size_t)NN * NH;
constexpr size_t OFF_WFOLD = OFF_U     + 64;                    // 256*6 + pad
constexpr size_t OFF_WT    = OFF_WFOLD + 1600;                  // 768*1024
constexpr size_t OFF_BSUM  = OFF_WT    + (size_t)768 * 1024;
constexpr size_t OFF_C     = OFF_BSUM  + 1024;
constexpr size_t OFF_QS    = OFF_C     + (size_t)GG * HH;
constexpr size_t OFF_Z     = OFF_QS    + (size_t)GG * 2 * HH;
constexpr size_t OFF_GATES = OFF_Z     + (size_t)GG * 768;
constexpr size_t OFF_E     = OFF_GATES + (size_t)GG * 1024;
constexpr size_t OFF_BND   = OFF_E     + NN;                    // 513 ints (as floats)
constexpr size_t TOTAL_F   = OFF_BND   + 520;

__device__ float g_scratch[TOTAL_F];

// ---------------- helpers ----------------
__device__ __forceinline__ float sigmoidf_(float x) { return 1.0f / (1.0f + expf(-x)); }

__device__ __forceinline__ void atomicMaxFloat(float* addr, float val) {
    int* ia = (int*)addr;
    int old = *ia;
    while (__int_as_float(old) < val) {
        int assumed = old;
        old = atomicCAS(ia, assumed, __float_as_int(val));
        if (old == assumed) break;
    }
}

__device__ __forceinline__ unsigned f2tf32(float x) {
    unsigned r;
    asm("cvt.rna.tf32.f32 %0, %1;" : "=r"(r) : "f"(x));
    return r;
}

__device__ __forceinline__ void split_tf32(float x, unsigned& hi, unsigned& lo) {
    hi = f2tf32(x);
    lo = f2tf32(x - __uint_as_float(hi));
}

__device__ __forceinline__ void mma_tf32(float* c, const unsigned* a, const unsigned* b) {
    asm volatile(
        "mma.sync.aligned.m16n8k8.row.col.f32.tf32.tf32.f32 "
        "{%0,%1,%2,%3}, {%4,%5,%6,%7}, {%8,%9}, {%0,%1,%2,%3};\n"
        : "+f"(c[0]), "+f"(c[1]), "+f"(c[2]), "+f"(c[3])
        : "r"(a[0]), "r"(a[1]), "r"(a[2]), "r"(a[3]), "r"(b[0]), "r"(b[1]));
}

// ---------- 3xTF32 tensor-core GEMM, BM=128 BN=64, 2 CTAs/SM: C = A[M,K]@B[K,N] ----------
// 8 warps in 4(m) x 2(n); warp tile 32x32. A: fp32 smem, split at fragment load.
// B: pre-split hi/lo smem (split once at tile store -> no redundant inner-loop B splits).
// Requires N % 64 == 0, K % 16 == 0.
// mode 0: C = AB ; 1: C = celu(AB+bias) ; 2: C = C + AB + bias ; 3: C = AB + bias
__global__ void __launch_bounds__(256, 2)
sgemm_tc(const float* __restrict__ A, const float* __restrict__ B,
         float* __restrict__ C, int M, int N, int K,
         const float* __restrict__ bias, int mode) {
    constexpr int BM = 128, BN = 64, BK = 16, SA = BM + 8, SB = BN + 8;
    __shared__ float As[2][BK][SA];
    __shared__ unsigned Bh_s[2][BK][SB];
    __shared__ unsigned Bl_s[2][BK][SB];

    const int tid  = threadIdx.x;
    const int warp = tid >> 5, lane = tid & 31;
    const int gid  = lane >> 2, tig = lane & 3;
    const int wm   = (warp & 3) * 32;   // 4 warps along M
    const int wn   = (warp >> 2) * 32;  // 2 warps along N
    const int bm   = blockIdx.y * BM;
    const int bn   = blockIdx.x * BN;

    float acc[2][4][4];
#pragma unroll
    for (int mt = 0; mt < 2; mt++)
#pragma unroll
        for (int nt = 0; nt < 4; nt++)
#pragma unroll
            for (int r = 0; r < 4; r++) acc[mt][nt][r] = 0.f;

    float4 a_reg[2], b_reg;

    auto loadA = [&](int k0) {
#pragma unroll
        for (int j = 0; j < 2; j++) {
            int f = tid + j * 256;          // 0..511
            int row = f >> 2;               // 0..127
            int c4 = (f & 3) << 2;          // 0,4,8,12
            if (bm + row < M)
                a_reg[j] = *(const float4*)(A + (size_t)(bm + row) * K + k0 + c4);
            else
                a_reg[j] = make_float4(0.f, 0.f, 0.f, 0.f);
        }
    };
    auto storeA = [&](int buf) {
#pragma unroll
        for (int j = 0; j < 2; j++) {
            int f = tid + j * 256;
            int row = f >> 2;
            int c4 = (f & 3) << 2;
            As[buf][c4 + 0][row] = a_reg[j].x;
            As[buf][c4 + 1][row] = a_reg[j].y;
            As[buf][c4 + 2][row] = a_reg[j].z;
            As[buf][c4 + 3][row] = a_reg[j].w;
        }
    };
    auto loadB = [&](int k0) {
        int krow = tid >> 4;                // 0..15
        int c4 = (tid & 15) << 2;           // 0..60
        b_reg = *(const float4*)(B + (size_t)(k0 + krow) * N + bn + c4);
    };
    auto storeB = [&](int buf) {
        int krow = tid >> 4;
        int c4 = (tid & 15) << 2;
        uint4 uh, ul;
        split_tf32(b_reg.x, uh.x, ul.x);
        split_tf32(b_reg.y, uh.y, ul.y);
        split_tf32(b_reg.z, uh.z, ul.z);
        split_tf32(b_reg.w, uh.w, ul.w);
        *(uint4*)&Bh_s[buf][krow][c4] = uh;
        *(uint4*)&Bl_s[buf][krow][c4] = ul;
    };

    const int KT = K / BK;
    loadA(0); loadB(0);
    storeA(0); storeB(0);
    __syncthreads();

    int cur = 0;
    for (int t = 0; t < KT; t++) {
        if (t + 1 < KT) { loadA((t + 1) * BK); loadB((t + 1) * BK); }
#pragma unroll
        for (int ks = 0; ks < 2; ks++) {
            int k0 = ks * 8;
            unsigned ah[2][4], al[2][4], bh[4][2], bl[4][2];
#pragma unroll
            for (int mt = 0; mt < 2; mt++) {
                int m0 = wm + mt * 16 + gid;
                float r0 = As[cur][k0 + tig    ][m0];
                float r1 = As[cur][k0 + tig    ][m0 + 8];
                float r2 = As[cur][k0 + tig + 4][m0];
                float r3 = As[cur][k0 + tig + 4][m0 + 8];
                split_tf32(r0, ah[mt][0], al[mt][0]);
                split_tf32(r1, ah[mt][1], al[mt][1]);
                split_tf32(r2, ah[mt][2], al[mt][2]);
                split_tf32(r3, ah[mt][3], al[mt][3]);
            }
#pragma unroll
            for (int nt = 0; nt < 4; nt++) {
                int n0 = wn + nt * 8 + gid;
                bh[nt][0] = Bh_s[cur][k0 + tig    ][n0];
                bh[nt][1] = Bh_s[cur][k0 + tig + 4][n0];
                bl[nt][0] = Bl_s[cur][k0 + tig    ][n0];
                bl[nt][1] = Bl_s[cur][k0 + tig + 4][n0];
            }
#pragma unroll
            for (int mt = 0; mt < 2; mt++)
#pragma unroll
                for (int nt = 0; nt < 4; nt++) {
                    mma_tf32(acc[mt][nt], al[mt], bh[nt]);
                    mma_tf32(acc[mt][nt], ah[mt], bl[nt]);
                    mma_tf32(acc[mt][nt], ah[mt], bh[nt]);
                }
        }
        if (t + 1 < KT) {
            storeA(cur ^ 1); storeB(cur ^ 1);
            __syncthreads();
            cur ^= 1;
        }
    }

    // epilogue
#pragma unroll
    for (int mt = 0; mt < 2; mt++) {
#pragma unroll
        for (int nt = 0; nt < 4; nt++) {
            int col = bn + wn + nt * 8 + 2 * tig;
            float bv0 = 0.f, bv1 = 0.f;
            if (mode != 0) { bv0 = bias[col]; bv1 = bias[col + 1]; }
#pragma unroll
            for (int half = 0; half < 2; half++) {
                int row = bm + wm + mt * 16 + gid + half * 8;
                if (row >= M) continue;
                float v0 = acc[mt][nt][half * 2 + 0];
                float v1 = acc[mt][nt][half * 2 + 1];
                size_t cidx = (size_t)row * N + col;
                if (mode == 1) {
                    v0 += bv0; v1 += bv1;
                    v0 = v0 > 0.f ? v0 : expm1f(v0);
                    v1 = v1 > 0.f ? v1 : expm1f(v1);
                } else if (mode == 2) {
                    v0 += bv0 + C[cidx]; v1 += bv1 + C[cidx + 1];
                } else if (mode == 3) {
                    v0 += bv0; v1 += bv1;
                }
                *(float2*)(C + cidx) = make_float2(v0, v1);
            }
        }
    }
}

// ---------------- folded attention score weights ----------------
// wfold[k, h*2+0] = sum_d Wn_l[k, h*H+d] * wa[h, d]        (dst)
// wfold[k, h*2+1] = sum_d Wn_l[k, h*H+d] * wa[h, 2H+d]     (src)
__global__ void fold_w_kernel(const float* __restrict__ Wn_l, const float* __restrict__ watt_l,
                              float* __restrict__ wfold) {
    int i = blockIdx.x * blockDim.x + threadIdx.x;
    if (i >= HH * 6) return;
    int k = i / 6, j = i - k * 6;
    int h = j >> 1, w = j & 1;
    const float* wn = Wn_l + (size_t)k * H3 + h * HH;
    const float* wa = watt_l + h * 3 * HH + (w ? 2 * HH : 0);
    float a = 0.f;
    for (int d = 0; d < HH; d++) a += wn[d] * wa[d];
    wfold[k * 6 + j] = a;
}

// per-node scores from out (1 KB/node instead of 3 KB xn row): warp per node, 6 dots
__global__ void node_scores_kernel(const float* __restrict__ out, const float* __restrict__ wfold,
                                   float* __restrict__ sdst, float* __restrict__ ssrc) {
    int warp = (blockIdx.x * blockDim.x + threadIdx.x) >> 5;
    int lane = threadIdx.x & 31;
    if (warp >= NN) return;
    const float* orow = out + (size_t)warp * HH;
    float acc[6] = {0.f, 0.f, 0.f, 0.f, 0.f, 0.f};
    for (int d = lane; d < HH; d += 32) {
        float v = orow[d];
        const float* wf = wfold + d * 6;
#pragma unroll
        for (int j = 0; j < 6; j++) acc[j] += v * wf[j];
    }
#pragma unroll
    for (int o = 16; o; o >>= 1)
#pragma unroll
        for (int j = 0; j < 6; j++) acc[j] += __shfl_down_sync(0xffffffffu, acc[j], o);
    if (!lane) {
#pragma unroll
        for (int h = 0; h < NH; h++) {
            sdst[warp * NH + h] = acc[h * 2];
            ssrc[warp * NH + h] = acc[h * 2 + 1];
        }
    }
}

// u[k,h] = sum_d We_l[k, h*H+d] * wa[h, H+d]
__global__ void compute_u_kernel(const float* __restrict__ We_l, const float* __restrict__ watt_l,
                                 float* __restrict__ u) {
    int warp = (blockIdx.x * blockDim.x + threadIdx.x) >> 5;
    int lane = threadIdx.x & 31;
    if (warp >= EFD * NH) return;
    int k = warp / NH, h = warp % NH;
    const float* wr = We_l + (size_t)k * H3 + h * HH;
    const float* wa = watt_l + h * 3 * HH + HH;
    float a = 0.f;
    for (int d = lane; d < HH; d += 32) a += wr[d] * wa[d];
#pragma unroll
    for (int o = 16; o; o >>= 1) a += __shfl_down_sync(0xffffffffu, a, o);
    if (!lane) u[k * NH + h] = a;
}

__global__ void init_nodesm_kernel(float* __restrict__ nmax, float* __restrict__ nsum) {
    int i = blockIdx.x * blockDim.x + threadIdx.x;
    if (i >= NN * NH) return;
    nmax[i] = __int_as_float(0xff800000); // -inf
    nsum[i] = 0.f;
}

// raw attention logits + leaky relu + segment max
__global__ void edge_alpha_kernel(const float* __restrict__ edge_attr,
                                  const int* __restrict__ src, const int* __restrict__ dst,
                                  const float* __restrict__ sdst, const float* __restrict__ ssrc,
                                  const float* __restrict__ u,
                                  float* __restrict__ alpha, float* __restrict__ nmax) {
    int e = blockIdx.x * blockDim.x + threadIdx.x;
    if (e >= EE) return;
    float ea[EFD];
#pragma unroll
    for (int k = 0; k < EFD; k++) ea[k] = edge_attr[(size_t)e * EFD + k];
    int s = src[e], t = dst[e];
#pragma unroll
    for (int h = 0; h < NH; h++) {
        float v = sdst[t * NH + h] + ssrc[s * NH + h];
#pragma unroll
        for (int k = 0; k < EFD; k++) v += ea[k] * u[k * NH + h];
        v = v > 0.f ? v : 0.2f * v;   // leaky_relu(0.2)
        alpha[(size_t)e * NH + h] = v;
        atomicMaxFloat(&nmax[t * NH + h], v);
    }
}

__global__ void edge_exp_kernel(const int* __restrict__ dst, float* __restrict__ alpha,
                                const float* __restrict__ nmax, float* __restrict__ nsum) {
    int i = blockIdx.x * blockDim.x + threadIdx.x;
    if (i >= EE * NH) return;
    int e = i / NH, h = i - e * NH;
    int t = dst[e];
    float ex = expf(alpha[i] - nmax[t * NH + h]);
    alpha[i] = ex;
    atomicAdd(&nsum[t * NH + h], ex);
}

// nsum -> 1/(nsum + eps), in place (NN*NH elements)
__global__ void nsum_inv_kernel(float* __restrict__ nsum) {
    int i = blockIdx.x * blockDim.x + threadIdx.x;
    if (i >= NN * NH) return;
    nsum[i] = 1.f / (nsum[i] + 1e-16f);
}

// per-edge message with vector reductions: aggr[dst] += alpha*ninv * ea * xn[src]
// 192 threads: thread owns 4 consecutive dims (one head each), red.global.add.v4.f32
__global__ void __launch_bounds__(192)
message_kernel(const float* __restrict__ xn, const float* __restrict__ edge_attr,
               const float* __restrict__ We_l, const float* __restrict__ alpha,
               const float* __restrict__ ninv,
               const int* __restrict__ src, const int* __restrict__ dst,
               float* __restrict__ aggr) {
    constexpr int EPB = 32;
    __shared__ float We_s[EFD * H3]; // 49152 bytes
    int tid = threadIdx.x;           // 0..191
    for (int i = tid; i < EFD * H3; i += 192) We_s[i] = We_l[i];
    __syncthreads();
    const float4* We4 = (const float4*)We_s;
    const int d4 = tid * 4;          // dim base, 0..764
    const int head = d4 >> 8;        // 0..2
    int e0 = blockIdx.x * EPB;
    int e1 = min(e0 + EPB, EE);
    for (int e = e0; e < e1; e++) {
        int s = src[e], t = dst[e];
        const float4* e4p = (const float4*)(edge_attr + (size_t)e * EFD);
        float4 q0 = e4p[0], q1 = e4p[1], q2 = e4p[2], q3 = e4p[3];
        float ea[EFD] = {q0.x, q0.y, q0.z, q0.w, q1.x, q1.y, q1.z, q1.w,
                         q2.x, q2.y, q2.z, q2.w, q3.x, q3.y, q3.z, q3.w};
        float coef = alpha[(size_t)e * NH + head] * ninv[t * NH + head];
        float4 eav = make_float4(0.f, 0.f, 0.f, 0.f);
#pragma unroll
        for (int k = 0; k < EFD; k++) {
            float4 wv = We4[k * (H3 / 4) + tid];
            eav.x += ea[k] * wv.x;
            eav.y += ea[k] * wv.y;
            eav.z += ea[k] * wv.z;
            eav.w += ea[k] * wv.w;
        }
        float4 xv = *(const float4*)(xn + (size_t)s * H3 + d4);
        float4 val;
        val.x = coef * eav.x * xv.x;
        val.y = coef * eav.y * xv.y;
        val.z = coef * eav.z * xv.z;
        val.w = coef * eav.w * xv.w;
        float* addr = aggr + (size_t)t * H3 + d4;
        asm volatile("red.global.add.v4.f32 [%0], {%1, %2, %3, %4};"
                     :: "l"(addr), "f"(val.x), "f"(val.y), "f"(val.z), "f"(val.w)
                     : "memory");
    }
}

// ---------------- set2set ----------------
__global__ void transpose_w_kernel(const float* __restrict__ W_ih, const float* __restrict__ W_hh,
                                   float* __restrict__ Wt) {
    int i = blockIdx.x * blockDim.x + threadIdx.x; // 768*1024
    if (i >= 768 * 1024) return;
    int k = i >> 10, j = i & 1023;
    Wt[i] = (k < 512) ? W_ih[(size_t)j * 512 + k] : W_hh[(size_t)j * 256 + (k - 512)];
}

__global__ void bias_sum_kernel(const float* __restrict__ b_ih, const float* __restrict__ b_hh,
                                float* __restrict__ bsum) {
    int j = blockIdx.x * blockDim.x + threadIdx.x;
    if (j < 1024) bsum[j] = b_ih[j] + b_hh[j];
}

// per-graph node range via binary search (batch is sorted)
__global__ void bounds_kernel(const int* __restrict__ batch, int* __restrict__ bounds) {
    int g = blockIdx.x * blockDim.x + threadIdx.x;
    if (g > GG) return;
    int lo = 0, hi = NN;
    while (lo < hi) { int mid = (lo + hi) >> 1; if (batch[mid] < g) lo = mid + 1; else hi = mid; }
    bounds[g] = lo;
}

// fused per-graph: LSTM cell + scores + segment softmax + pooling + q_star/z packing
__global__ void s2s_step_kernel(const float* __restrict__ gates, float* __restrict__ c,
                                const float* __restrict__ out, const int* __restrict__ bounds,
                                float* __restrict__ e_buf, float* __restrict__ z,
                                float* __restrict__ qstar) {
    int g = blockIdx.x, tid = threadIdx.x;      // 512 blocks x 256
    int lane = tid & 31, wid = tid >> 5;
    __shared__ float hs[HH];
    __shared__ float red[8];
    __shared__ float m_s, sum_s;
    int s0 = bounds[g], s1 = bounds[g + 1];

    // LSTM cell (pytorch gate order i,f,g,o)
    const float* gr = gates + (size_t)g * 1024;
    float ii = sigmoidf_(gr[tid]);
    float ff = sigmoidf_(gr[256 + tid]);
    float gg = tanhf(gr[512 + tid]);
    float oo = sigmoidf_(gr[768 + tid]);
    size_t cidx = (size_t)g * 256 + tid;
    float cn = ff * c[cidx] + ii * gg;
    c[cidx] = cn;
    float hv = oo * tanhf(cn);
    hs[tid] = hv;
    __syncthreads();

    // pass 1: e[n] = out[n].h ; block max
    float lmax = __int_as_float(0xff800000);
    for (int n = s0 + wid; n < s1; n += 8) {
        const float* orow = out + (size_t)n * HH;
        float a = 0.f;
        for (int d = lane; d < HH; d += 32) a += orow[d] * hs[d];
#pragma unroll
        for (int o = 16; o; o >>= 1) a += __shfl_down_sync(0xffffffffu, a, o);
        if (!lane) { e_buf[n] = a; lmax = fmaxf(lmax, a); }
    }
    if (!lane) red[wid] = lmax;
    __syncthreads();
    if (tid == 0) {
        float m = red[0];
        for (int w = 1; w < 8; w++) m = fmaxf(m, red[w]);
        if (!isfinite(m)) m = 0.f;
        m_s = m;
    }
    __syncthreads();
    float m = m_s;

    // pass 2: ex = exp(e - m); block sum
    float ls = 0.f;
    for (int n = s0 + tid; n < s1; n += 256) {
        float ex = expf(e_buf[n] - m);
        e_buf[n] = ex;
        ls += ex;
    }
#pragma unroll
    for (int o = 16; o; o >>= 1) ls += __shfl_down_sync(0xffffffffu, ls, o);
    if (!lane) red[wid] = ls;
    __syncthreads();
    if (tid == 0) {
        float s = 0.f;
        for (int w = 0; w < 8; w++) s += red[w];
        sum_s = s;
    }
    __syncthreads();
    float inv = 1.f / (sum_s + 1e-16f);

    // pass 3: r[d] = sum_n ex[n]*out[n][d] * inv
    float r = 0.f;
    int n = s0;
    for (; n + 4 <= s1; n += 4) {
        r += e_buf[n]     * out[(size_t)n * HH + tid]
           + e_buf[n + 1] * out[(size_t)(n + 1) * HH + tid]
           + e_buf[n + 2] * out[(size_t)(n + 2) * HH + tid]
           + e_buf[n + 3] * out[(size_t)(n + 3) * HH + tid];
    }
    for (; n < s1; n++) r += e_buf[n] * out[(size_t)n * HH + tid];
    r *= inv;

    qstar[(size_t)g * 512 + tid]       = hv;
    qstar[(size_t)g * 512 + 256 + tid] = r;
    z[(size_t)g * 768 + tid]           = hv;  // z = [q_star, h] = [h, r, h]
    z[(size_t)g * 768 + 256 + tid]     = r;
    z[(size_t)g * 768 + 512 + tid]     = hv;
}

// ---------------- MLP head: Linear -> LayerNorm -> ReLU -> Linear ----------------
__global__ void head_kernel(const float* __restrict__ qstar, const float* __restrict__ W1,
                            const float* __restrict__ b1, const float* __restrict__ ln_g,
                            const float* __restrict__ ln_b, const float* __restrict__ W2,
                            const float* __restrict__ b2, float* __restrict__ outp) {
    __shared__ float qs[512];
    __shared__ float r1[8], r2[8];
    __shared__ float stats[2];
    __shared__ float accs[OUTF];
    int g = blockIdx.x, tid = threadIdx.x; // 512 blocks x 256
    qs[tid]       = qstar[(size_t)g * 512 + tid];
    qs[tid + 256] = qstar[(size_t)g * 512 + 256 + tid];
    if (tid < OUTF) accs[tid] = 0.f;
    __syncthreads();

    float v = b1[tid];
    for (int k = 0; k < 512; k++) v += qs[k] * W1[(size_t)k * 256 + tid];

    int lane = tid & 31, wid = tid >> 5;
    float s1 = v, s2 = v * v;
#pragma unroll
    for (int o = 16; o; o >>= 1) {
        s1 += __shfl_down_sync(0xffffffffu, s1, o);
        s2 += __shfl_down_sync(0xffffffffu, s2, o);
    }
    if (!lane) { r1[wid] = s1; r2[wid] = s2; }
    __syncthreads();
    if (tid == 0) {
        float t1 = 0.f, t2 = 0.f;
        for (int w = 0; w < 8; w++) { t1 += r1[w]; t2 += r2[w]; }
        float mu = t1 / 256.f;
        float var = t2 / 256.f - mu * mu;
        stats[0] = mu;
        stats[1] = rsqrtf(var + 1e-5f);
    }
    __syncthreads();

    float yln = (v - stats[0]) * stats[1] * ln_g[tid] + ln_b[tid];
    yln = fmaxf(yln, 0.f);

    float p[OUTF];
#pragma unroll
    for (int j = 0; j < OUTF; j++) p[j] = yln * W2[(size_t)tid * OUTF + j];
#pragma unroll
    for (int o = 16; o; o >>= 1)
#pragma unroll
        for (int j = 0; j < OUTF; j++) p[j] += __shfl_down_sync(0xffffffffu, p[j], o);
    if (!lane)
        for (int j = 0; j < OUTF; j++) atomicAdd(&accs[j], p[j]);
    __syncthreads();
    if (tid < OUTF) outp[(size_t)g * OUTF + tid] = accs[tid] + b2[tid];
}

// ---------------- host orchestration ----------------
static void launch_gemm(const float* A, const float* B, float* C, int M, int N, int K,
                        const float* bias, int mode) {
    dim3 grid(N / 64, (M + 127) / 128);
    sgemm_tc<<<grid, 256>>>(A, B, C, M, N, K, bias, mode);
}

extern "C" void kernel_launch(void* const* d_in, const int* in_sizes, int n_in,
                              void* d_out, int out_size) {
    const float* x         = (const float*)d_in[0];
    const float* edge_attr = (const float*)d_in[1];
    const int*   edge_index= (const int*)d_in[2];
    const int*   batch     = (const int*)d_in[3];
    const float* proj_W    = (const float*)d_in[4];
    const float* proj_b    = (const float*)d_in[5];
    const float* Wn        = (const float*)d_in[6];
    const float* We        = (const float*)d_in[7];
    const float* Watt      = (const float*)d_in[8];
    const float* Ws        = (const float*)d_in[9];
    const float* bl        = (const float*)d_in[10];
    const float* W_ih      = (const float*)d_in[11];
    const float* W_hh      = (const float*)d_in[12];
    const float* b_ih      = (const float*)d_in[13];
    const float* b_hh      = (const float*)d_in[14];
    const float* mlp_W1    = (const float*)d_in[15];
    const float* mlp_b1    = (const float*)d_in[16];
    const float* ln_g      = (const float*)d_in[17];
    const float* ln_b      = (const float*)d_in[18];
    const float* mlp_W2    = (const float*)d_in[19];
    const float* mlp_b2    = (const float*)d_in[20];
    float* outp = (float*)d_out;

    const int* src = edge_index;
    const int* dst = edge_index + EE;

    float* S = nullptr;
    cudaGetSymbolAddress((void**)&S, g_scratch);
    float* out_   = S + OFF_OUT;
    float* xn_    = S + OFF_XN;
    float* aggr_  = S + OFF_AGGR;
    float* sdst_  = S + OFF_SDST;
    float* ssrc_  = S + OFF_SSRC;
    float* alpha_ = S + OFF_ALPHA;
    float* nmax_  = S + OFF_NMAX;
    float* nsum_  = S + OFF_NSUM;
    float* u_     = S + OFF_U;
    float* wfold_ = S + OFF_WFOLD;
    float* wt_    = S + OFF_WT;
    float* bsum_  = S + OFF_BSUM;
    float* c_     = S + OFF_C;
    float* qs_    = S + OFF_QS;
    float* z_     = S + OFF_Z;
    float* gates_ = S + OFF_GATES;
    float* e_     = S + OFF_E;
    int*   bnd_   = (int*)(S + OFF_BND);

    // ---- projection: out = celu(x @ proj_W + proj_b) ----
    launch_gemm(x, proj_W, out_, NN, HH, INF_, proj_b, 1);

    // ---- 3 triplet message-passing layers ----
    for (int l = 0; l < LAY; l++) {
        const float* Wn_l = Wn   + (size_t)l * HH * H3;
        const float* We_l = We   + (size_t)l * EFD * H3;
        const float* Wa_l = Watt + (size_t)l * NH * 3 * HH;
        const float* Ws_l = Ws   + (size_t)l * H3 * HH;
        const float* bl_l = bl   + (size_t)l * HH;

        launch_gemm(out_, Wn_l, xn_, NN, H3, HH, nullptr, 0);
        fold_w_kernel<<<6, 256>>>(Wn_l, Wa_l, wfold_);
        node_scores_kernel<<<(NN * 32 + 255) / 256, 256>>>(out_, wfold_, sdst_, ssrc_);
        compute_u_kernel<<<6, 256>>>(We_l, Wa_l, u_);
        init_nodesm_kernel<<<(NN * NH + 255) / 256, 256>>>(nmax_, nsum_);
        edge_alpha_kernel<<<(EE + 255) / 256, 256>>>(edge_attr, src, dst, sdst_, ssrc_, u_,
                                                     alpha_, nmax_);
        edge_exp_kernel<<<(EE * NH + 255) / 256, 256>>>(dst, alpha_, nmax_, nsum_);
        nsum_inv_kernel<<<(NN * NH + 255) / 256, 256>>>(nsum_);
        cudaMemsetAsync(aggr_, 0, (size_t)NN * H3 * sizeof(float));
        message_kernel<<<(EE + 31) / 32, 192>>>(xn_, edge_attr, We_l, alpha_, nsum_, src, dst,
                                                aggr_);
        launch_gemm(aggr_, Ws_l, out_, NN, HH, H3, bl_l, 2);
    }

    // ---- set2set ----
    transpose_w_kernel<<<(768 * 1024 + 255) / 256, 256>>>(W_ih, W_hh, wt_);
    bias_sum_kernel<<<4, 256>>>(b_ih, b_hh, bsum_);
    bounds_kernel<<<3, 256>>>(batch, bnd_);
    cudaMemsetAsync(c_, 0, (size_t)GG * HH * sizeof(float));
    cudaMemsetAsync(z_, 0, (size_t)GG * 768 * sizeof(float));

    for (int s = 0; s < STEP; s++) {
        launch_gemm(z_, wt_, gates_, GG, 1024, 768, bsum_, 3);
        s2s_step_kernel<<<GG, 256>>>(gates_, c_, out_, bnd_, e_, z_, qs_);
    }

    // ---- MLP head ----
    head_kernel<<<GG, 256>>>(qs_, mlp_W1, mlp_b1, ln_g, ln_b, mlp_W2, mlp_b2, outp);
}